// round 15
// baseline (speedup 1.0000x reference)
#include <cuda_runtime.h>
#include <cuda_fp16.h>

#define BB 16
#define CC 3
#define HH 256
#define WW 256
#define MM 100
#define HW (HH * WW)

// Corner-major, interleaved 32B cells, zero-halo padded (layout as R11-R14).
#define NE 259
#define NR 259
#define STRE 264
__device__ uint4 g_cell[BB * 260 * STRE * 2];

__device__ __forceinline__ unsigned packh2(float a, float b) {
    __half2 h = __halves2half2(__float2half(a), __float2half(b));
    return *reinterpret_cast<unsigned*>(&h);
}

// Shfl-based pack: block = 9 warps, one padded row (ey, b) per block.
__global__ void __launch_bounds__(288) pack_kernel(const float* __restrict__ x) {
    int w = threadIdx.x >> 5;
    int l = threadIdx.x & 31;
    int ey = blockIdx.y;
    int b = blockIdx.z;
    int c = w * 31 + l - 2;
    int y0 = ey - 2;

    float v[6] = {0.f, 0.f, 0.f, 0.f, 0.f, 0.f};
    bool cx = ((unsigned)c < (unsigned)WW);
    const float* xb = x + (size_t)b * CC * HW + c;
    if (cx && (unsigned)y0 < (unsigned)HH) {
        const float* p = xb + y0 * WW;
        v[0] = p[0]; v[1] = p[HW]; v[2] = p[2 * HW];
    }
    if (cx && (unsigned)(y0 + 1) < (unsigned)HH) {
        const float* p = xb + (y0 + 1) * WW;
        v[3] = p[0]; v[4] = p[HW]; v[5] = p[2 * HW];
    }

    float n[6];
#pragma unroll
    for (int k = 0; k < 6; k++)
        n[k] = __shfl_up_sync(0xffffffffu, v[k], 1);

    int ex = c + 1;
    if (l >= 1 && (unsigned)ex <= (unsigned)(NE - 1)) {
        int idx = (b * 260 + ey) * STRE + ex;
        uint4 q;
        q.x = packh2(n[0], v[0]);
        q.y = packh2(n[3], v[3]);
        q.z = packh2(n[1], v[1]);
        q.w = packh2(n[4], v[4]);
        g_cell[2 * idx] = q;
        uint2 r;
        r.x = packh2(n[2], v[2]);
        r.y = packh2(n[5], v[5]);
        *reinterpret_cast<uint2*>(&g_cell[2 * idx + 1]) = r;
    }
}

__device__ __forceinline__ __half2 u2h(unsigned u) {
    return *reinterpret_cast<const __half2*>(&u);
}

// Tap loop over ky = slice, slice+4, slice+8. CLAMP=false for interior warps.
template <bool CLAMP>
__device__ __forceinline__ void tap_loop(
    int slice, float ixb, float iyb, float ux, float uy, float vx, float vy,
    const char* __restrict__ base, float& acc0, float& acc1, float& acc2)
{
    const __half2 hz = __float2half2_rn(0.0f);
    const float c_wk_lit[11] = {0.00386592f, 0.02856550f, 0.13533528f,
                                0.41111229f, 0.80073740f, 1.0f,
                                0.80073740f, 0.41111229f, 0.13533528f,
                                0.02856550f, 0.00386592f};
    int idx_prev = -1;
    uint4 q = make_uint4(0u, 0u, 0u, 0u);
    uint2 r = make_uint2(0u, 0u);

#pragma unroll 1
    for (int ky = slice; ky < 11; ky += 4) {
        float dky = (float)(ky - 5);
        float wyk = c_wk_lit[ky];
        float ixr = fmaf(dky, vx, ixb);
        float iyr = fmaf(dky, vy, iyb);

        __half2 ra = hz, rb = hz, r2 = hz;

#pragma unroll
        for (int kx = 0; kx < 11; kx++) {
            const float wkx_lit[11] = {0.00386592f, 0.02856550f, 0.13533528f,
                                       0.41111229f, 0.80073740f, 1.0f,
                                       0.80073740f, 0.41111229f, 0.13533528f,
                                       0.02856550f, 0.00386592f};
            float dkx = (float)(kx - 5);
            float ix = fmaf(dkx, ux, ixr);
            float iy = fmaf(dkx, uy, iyr);

            float ixc = ix, iyc = iy;
            if (CLAMP) {
                ixc = fminf(fmaxf(ix, 0.0f), 258.5f);
                iyc = fminf(fmaxf(iy, 0.0f), 258.5f);
            }
            float x0f = floorf(ixc);
            float y0f = floorf(iyc);
            float fx = ixc - x0f;
            float fy = iyc - y0f;
            int idx = (int)fmaf(y0f, (float)STRE, x0f);

            const char* pa = base + (size_t)idx * 32;
            asm("{\n\t"
                ".reg .pred p;\n\t"
                "setp.ne.s32 p, %7, %8;\n\t"
                "@p ld.global.nc.v4.u32 {%0,%1,%2,%3}, [%6];\n\t"
                "@p ld.global.nc.v2.u32 {%4,%5}, [%6+16];\n\t"
                "}"
                : "+r"(q.x), "+r"(q.y), "+r"(q.z), "+r"(q.w),
                  "+r"(r.x), "+r"(r.y)
                : "l"(pa), "r"(idx), "r"(idx_prev));
            idx_prev = idx;

            float wgt = wyk * wkx_lit[kx];
            float a0 = fmaf(-wgt, fy, wgt);
            float a1 = wgt * fy;
            __half2 hfx = __floats2half2_rn(1.0f - fx, fx);
            __half2 wp0 = __hmul2(__float2half2_rn(a0), hfx);
            __half2 wp1 = __hmul2(__float2half2_rn(a1), hfx);

            ra = __hfma2(wp0, u2h(q.x), ra);
            ra = __hfma2(wp1, u2h(q.y), ra);
            rb = __hfma2(wp0, u2h(q.z), rb);
            rb = __hfma2(wp1, u2h(q.w), rb);
            r2 = __hfma2(wp0, u2h(r.x), r2);
            r2 = __hfma2(wp1, u2h(r.y), r2);
        }

        float2 fa = __half22float2(ra);
        float2 fb = __half22float2(rb);
        float2 f2 = __half22float2(r2);
        acc0 += fa.x + fa.y;
        acc1 += fb.x + fb.y;
        acc2 += f2.x + f2.y;
    }
}

// Block = 16 pixels (8 wide x 2 tall) x 4 ky-slices = 64 threads.
// 10400 tiles, scattered by a coprime multiplier for uniform live/dead mix.
__global__ void __launch_bounds__(64, 24) stn_kernel(const float* __restrict__ theta,
                                                     float* __restrict__ out) {
    int flat = blockIdx.x;
    int perm = (int)(((long long)flat * 3001) % 10400);  // gcd(3001,10400)=1
    int b = perm / 650;                                  // 650 = 50*13 tiles per batch
    int rest = perm - b * 650;
    int ti = rest / 13;                                  // 0..49 (rows of 2)
    int tj = rest - ti * 13;                             // 0..12 (cols of 8)

    int tid = threadIdx.x;
    int slice = tid & 3;
    int p = tid >> 2;                                    // 0..15
    int i = ti * 2 + (p >> 3);
    int j = tj * 8 + (p & 7);
    bool valid = (j < MM);
    j = min(j, MM - 1);

    const float* th = theta + b * 6;
    float t00 = __ldg(th + 0), t01 = __ldg(th + 1), t02 = __ldg(th + 2);
    float t10 = __ldg(th + 3), t11 = __ldg(th + 4), t12 = __ldg(th + 5);

    float lx = (j + 0.5f) * (2.0f / MM) - 1.0f;
    float ly = (i + 0.5f) * (2.0f / MM) - 1.0f;
    float gx = fmaf(t00, lx, fmaf(t01, ly, t02));
    float gy = fmaf(t10, lx, fmaf(t11, ly, t12));

    float ixb = fmaf(gx, 0.5f * WW, 0.5f * WW - 0.5f + 2.0f);
    float iyb = fmaf(gy, 0.5f * HH, 0.5f * HH - 0.5f + 2.0f);

    const float cstep = (0.5f * WW) / (6.0f * 99.0f);
    float ux = t00 * cstep, uy = t10 * cstep;
    float vx = t01 * cstep, vy = t11 * cstep;

    const float wsum = 3.75923278f;
    const float inv = 1.0f / (wsum * wsum);

    const char* __restrict__ base = (const char*)g_cell + (size_t)b * (260 * STRE * 32);

    float acc0 = 0.0f, acc1 = 0.0f, acc2 = 0.0f;

    float ex_x = 5.0f * (fabsf(ux) + fabsf(vx));
    float ex_y = 5.0f * (fabsf(uy) + fabsf(vy));
    bool dead = (ixb + ex_x <= 1.0f) || (ixb - ex_x >= 258.0f) ||
                (iyb + ex_y <= 1.0f) || (iyb - ex_y >= 258.0f);
    bool interior = (ixb - ex_x >= 0.0f) && (ixb + ex_x <= 258.0f) &&
                    (iyb - ex_y >= 0.0f) && (iyb + ex_y <= 258.0f);

    if (!__all_sync(0xffffffffu, dead)) {
        if (__all_sync(0xffffffffu, interior))
            tap_loop<false>(slice, ixb, iyb, ux, uy, vx, vy, base, acc0, acc1, acc2);
        else
            tap_loop<true>(slice, ixb, iyb, ux, uy, vx, vy, base, acc0, acc1, acc2);
    }

    acc0 += __shfl_xor_sync(0xffffffff, acc0, 1);
    acc1 += __shfl_xor_sync(0xffffffff, acc1, 1);
    acc2 += __shfl_xor_sync(0xffffffff, acc2, 1);
    acc0 += __shfl_xor_sync(0xffffffff, acc0, 2);
    acc1 += __shfl_xor_sync(0xffffffff, acc1, 2);
    acc2 += __shfl_xor_sync(0xffffffff, acc2, 2);

    if (slice == 0 && valid) {
        int rr = i * MM + j;
        float* ob = out + b * (CC * MM * MM) + rr;
        ob[0]           = acc0 * inv;
        ob[MM * MM]     = acc1 * inv;
        ob[2 * MM * MM] = acc2 * inv;
    }
}

extern "C" void kernel_launch(void* const* d_in, const int* in_sizes, int n_in,
                              void* d_out, int out_size) {
    const float* x = (const float*)d_in[0];
    const float* th = (const float*)d_in[1];
    if (n_in >= 2 && in_sizes[0] == 96) {
        x = (const float*)d_in[1];
        th = (const float*)d_in[0];
    }
    float* out = (float*)d_out;

    {
        dim3 grid(1, NR, BB);
        pack_kernel<<<grid, 288>>>(x);
    }
    {
        stn_kernel<<<10400, 64>>>(th, out);
    }
    (void)out_size;
}